// round 4
// baseline (speedup 1.0000x reference)
#include <cuda_runtime.h>
#include <cstdint>

#define N_ROWS  2048
#define D_DIM   512
#define H_DIM   512
#define N_HEADS 16

#define BM 64
#define BN 64
#define BK 32
#define NTILES (D_DIM / BK)   // 16

__device__ int g_perm[N_ROWS];
__device__ int g_off[N_HEADS + 1];

// ---------------------------------------------------------------------------
// Kernel 1: counting-sort rows by head. Handles idx as int32 or int64
// (device-side probe: int64 head values < 16 have all odd words zero).
// ---------------------------------------------------------------------------
__global__ void bucket_kernel(const int* __restrict__ idxw) {
    __shared__ int cnt[N_HEADS];
    __shared__ int cur[N_HEADS];
    __shared__ int offs[N_HEADS + 1];
    __shared__ int odd_nonzero;
    int tid = threadIdx.x;
    if (tid < N_HEADS) cnt[tid] = 0;
    if (tid == 0) odd_nonzero = 0;
    __syncthreads();

    int local = 0;
    for (int i = tid; i < N_ROWS / 2; i += blockDim.x)
        if (idxw[2 * i + 1] != 0) local = 1;
    if (local) atomicOr(&odd_nonzero, 1);
    __syncthreads();
    const bool is64 = (odd_nonzero == 0);

    for (int i = tid; i < N_ROWS; i += blockDim.x)
        atomicAdd(&cnt[is64 ? idxw[2 * i] : idxw[i]], 1);
    __syncthreads();
    if (tid == 0) {
        int acc = 0;
        for (int h = 0; h < N_HEADS; h++) {
            offs[h] = acc; cur[h] = acc; acc += cnt[h];
        }
        offs[N_HEADS] = acc;
    }
    __syncthreads();
    if (tid <= N_HEADS) g_off[tid] = offs[tid];
    for (int i = tid; i < N_ROWS; i += blockDim.x) {
        int h = is64 ? idxw[2 * i] : idxw[i];
        g_perm[atomicAdd(&cur[h], 1)] = i;
    }
}

// ---------------------------------------------------------------------------
// f32x2 + cp.async helpers
// ---------------------------------------------------------------------------
__device__ __forceinline__ unsigned long long fma2(unsigned long long a,
                                                   unsigned long long b,
                                                   unsigned long long c) {
    unsigned long long d;
    asm("fma.rn.f32x2 %0, %1, %2, %3;" : "=l"(d) : "l"(a), "l"(b), "l"(c));
    return d;
}
__device__ __forceinline__ unsigned long long pack2(float lo, float hi) {
    unsigned long long r;
    asm("mov.b64 %0, {%1, %2};" : "=l"(r) : "f"(lo), "f"(hi));
    return r;
}
__device__ __forceinline__ float2 unpack2(unsigned long long v) {
    float2 r;
    asm("mov.b64 {%0, %1}, %2;" : "=f"(r.x), "=f"(r.y) : "l"(v));
    return r;
}
__device__ __forceinline__ void cp16(void* smem_dst, const void* gmem_src) {
    unsigned s = (unsigned)__cvta_generic_to_shared(smem_dst);
    asm volatile("cp.async.ca.shared.global [%0], [%1], 16;" :: "r"(s), "l"(gmem_src));
}
__device__ __forceinline__ void cp_commit() {
    asm volatile("cp.async.commit_group;");
}
__device__ __forceinline__ void cp_wait0() {
    asm volatile("cp.async.wait_group 0;");
}

// ---------------------------------------------------------------------------
// Kernel 2: grouped GEMM, double-buffered.
// grid = (H/BN, N_HEADS, maxRowTiles); 256 threads; 4x4 microtile via FFMA2.
// ---------------------------------------------------------------------------
__global__ __launch_bounds__(256)
void multilinear_gemm(const float* __restrict__ X,
                      const float* __restrict__ W,
                      const float* __restrict__ B,
                      float* __restrict__ out) {
    const int h    = blockIdx.y;
    const int base = g_off[h];
    const int end  = g_off[h + 1];
    const int row0 = base + blockIdx.z * BM;
    if (row0 >= end) return;
    const int n0 = blockIdx.x * BN;

    // As2: a-values duplicated into f32x2 slots (kills pack MOVs in mainloop)
    __shared__ unsigned long long As2[2][BK][BM];   // 2 x 16 KB
    __shared__ float              Bs [2][BK][BN];   // 2 x  8 KB

    const int tid = threadIdx.x;
    const int tx  = tid & 15;       // n group (4 cols)
    const int ty  = tid >> 4;       // m group (4 rows)

    // X-load mapping: each thread owns row lm, k-chunks lk and lk+16
    const int lm = tid & 63;
    const int lk = (tid >> 6) * 4;  // 0,4,8,12
    // Bs cp.async mapping: row bk (0..31), 2x16B at col bn
    const int bk = tid >> 3;
    const int bn = (tid & 7) * 8;

    const float* Wh = W + (size_t)h * D_DIM * H_DIM;

    const int  mrow   = row0 + lm;
    const int  gr     = (mrow < end) ? g_perm[mrow] : 0;  // safe dummy row
    const float* Xrow = X + (size_t)gr * D_DIM;

    unsigned long long acc[4][2];
#pragma unroll
    for (int i = 0; i < 4; i++) { acc[i][0] = 0ull; acc[i][1] = 0ull; }

    // ---- prologue: tile 0 ----
    float4 xa = *reinterpret_cast<const float4*>(Xrow + lk);
    float4 xb = *reinterpret_cast<const float4*>(Xrow + 16 + lk);
    cp16(&Bs[0][bk][bn],     Wh + (size_t)bk * H_DIM + n0 + bn);
    cp16(&Bs[0][bk][bn + 4], Wh + (size_t)bk * H_DIM + n0 + bn + 4);
    cp_commit();
    {
        As2[0][lk + 0][lm] = pack2(xa.x, xa.x);
        As2[0][lk + 1][lm] = pack2(xa.y, xa.y);
        As2[0][lk + 2][lm] = pack2(xa.z, xa.z);
        As2[0][lk + 3][lm] = pack2(xa.w, xa.w);
        As2[0][lk + 16][lm] = pack2(xb.x, xb.x);
        As2[0][lk + 17][lm] = pack2(xb.y, xb.y);
        As2[0][lk + 18][lm] = pack2(xb.z, xb.z);
        As2[0][lk + 19][lm] = pack2(xb.w, xb.w);
    }
    cp_wait0();
    __syncthreads();

    for (int t = 0; t < NTILES; t++) {
        const int cur = t & 1;
        const int nxt = cur ^ 1;
        const int k1  = (t + 1) * BK;

        // issue next tile's loads before computing (latency hidden by compute)
        if (t + 1 < NTILES) {
            xa = *reinterpret_cast<const float4*>(Xrow + k1 + lk);
            xb = *reinterpret_cast<const float4*>(Xrow + k1 + 16 + lk);
            cp16(&Bs[nxt][bk][bn],     Wh + (size_t)(k1 + bk) * H_DIM + n0 + bn);
            cp16(&Bs[nxt][bk][bn + 4], Wh + (size_t)(k1 + bk) * H_DIM + n0 + bn + 4);
            cp_commit();
        }

#pragma unroll
        for (int kk = 0; kk < BK; kk++) {
            unsigned long long a0 = As2[cur][kk][ty * 4 + 0];
            unsigned long long a1 = As2[cur][kk][ty * 4 + 1];
            unsigned long long a2 = As2[cur][kk][ty * 4 + 2];
            unsigned long long a3 = As2[cur][kk][ty * 4 + 3];
            unsigned long long b0 = *reinterpret_cast<const unsigned long long*>(&Bs[cur][kk][tx * 4]);
            unsigned long long b1 = *reinterpret_cast<const unsigned long long*>(&Bs[cur][kk][tx * 4 + 2]);
            acc[0][0] = fma2(a0, b0, acc[0][0]);
            acc[0][1] = fma2(a0, b1, acc[0][1]);
            acc[1][0] = fma2(a1, b0, acc[1][0]);
            acc[1][1] = fma2(a1, b1, acc[1][1]);
            acc[2][0] = fma2(a2, b0, acc[2][0]);
            acc[2][1] = fma2(a2, b1, acc[2][1]);
            acc[3][0] = fma2(a3, b0, acc[3][0]);
            acc[3][1] = fma2(a3, b1, acc[3][1]);
        }

        if (t + 1 < NTILES) {
            As2[nxt][lk + 0][lm] = pack2(xa.x, xa.x);
            As2[nxt][lk + 1][lm] = pack2(xa.y, xa.y);
            As2[nxt][lk + 2][lm] = pack2(xa.z, xa.z);
            As2[nxt][lk + 3][lm] = pack2(xa.w, xa.w);
            As2[nxt][lk + 16][lm] = pack2(xb.x, xb.x);
            As2[nxt][lk + 17][lm] = pack2(xb.y, xb.y);
            As2[nxt][lk + 18][lm] = pack2(xb.z, xb.z);
            As2[nxt][lk + 19][lm] = pack2(xb.w, xb.w);
            cp_wait0();
        }
        __syncthreads();
    }

    // epilogue: bias + scatter back to original rows
    const int n = n0 + tx * 4;
    const float4 bias = *reinterpret_cast<const float4*>(B + (size_t)h * H_DIM + n);
#pragma unroll
    for (int i = 0; i < 4; i++) {
        int r = row0 + ty * 4 + i;
        if (r < end) {
            int orow = g_perm[r];
            float2 c0 = unpack2(acc[i][0]);
            float2 c1 = unpack2(acc[i][1]);
            float4 v  = make_float4(c0.x + bias.x, c0.y + bias.y,
                                    c1.x + bias.z, c1.y + bias.w);
            *reinterpret_cast<float4*>(out + (size_t)orow * H_DIM + n) = v;
        }
    }
}

// ---------------------------------------------------------------------------
extern "C" void kernel_launch(void* const* d_in, const int* in_sizes, int n_in,
                              void* d_out, int out_size) {
    // bind by element count (robust to ordering)
    const float* X = nullptr; const int* idx = nullptr;
    const float* W = nullptr; const float* B = nullptr;
    for (int i = 0; i < n_in; i++) {
        switch (in_sizes[i]) {
            case 1048576: X   = (const float*)d_in[i]; break;
            case 2048:    idx = (const int*)d_in[i];   break;
            case 4194304: W   = (const float*)d_in[i]; break;
            case 8192:    B   = (const float*)d_in[i]; break;
        }
    }
    float* out = (float*)d_out;

    bucket_kernel<<<1, 256>>>(idx);

    dim3 grid(H_DIM / BN, N_HEADS, N_ROWS / BM);
    multilinear_gemm<<<grid, 256>>>(X, W, B, out);
}

// round 9
// speedup vs baseline: 2.4046x; 2.4046x over previous
#include <cuda_runtime.h>
#include <cstdint>

#define N_ROWS  2048
#define D_DIM   512
#define H_DIM   512
#define N_HEADS 16

#define TM 64
#define TN 64
#define BK 32
#define KTILES (D_DIM / BK)   // 16

// padded smem strides (bf16 elements): conflict-free ldmatrix rows
#define ASTRIDE 40   // 80 B
#define WSTRIDE 72   // 144 B

__device__ int g_perm[N_ROWS];
__device__ int g_off[N_HEADS + 1];

// ---------------------------------------------------------------------------
// Kernel 1: counting-sort rows by head (idx int32 or int64, device probe)
// ---------------------------------------------------------------------------
__global__ void bucket_kernel(const int* __restrict__ idxw) {
    __shared__ int cnt[N_HEADS];
    __shared__ int cur[N_HEADS];
    __shared__ int offs[N_HEADS + 1];
    __shared__ int odd_nonzero;
    int tid = threadIdx.x;
    if (tid < N_HEADS) cnt[tid] = 0;
    if (tid == 0) odd_nonzero = 0;
    __syncthreads();
    int local = 0;
    for (int i = tid; i < N_ROWS / 2; i += blockDim.x)
        if (idxw[2 * i + 1] != 0) local = 1;
    if (local) atomicOr(&odd_nonzero, 1);
    __syncthreads();
    const bool is64 = (odd_nonzero == 0);
    for (int i = tid; i < N_ROWS; i += blockDim.x)
        atomicAdd(&cnt[is64 ? idxw[2 * i] : idxw[i]], 1);
    __syncthreads();
    if (tid == 0) {
        int acc = 0;
        for (int h = 0; h < N_HEADS; h++) { offs[h] = acc; cur[h] = acc; acc += cnt[h]; }
        offs[N_HEADS] = acc;
    }
    __syncthreads();
    if (tid <= N_HEADS) g_off[tid] = offs[tid];
    for (int i = tid; i < N_ROWS; i += blockDim.x) {
        int h = is64 ? idxw[2 * i] : idxw[i];
        g_perm[atomicAdd(&cur[h], 1)] = i;
    }
}

// ---------------------------------------------------------------------------
// PTX helpers (baseline ISA only — no "a"-suffix features)
// ---------------------------------------------------------------------------
__device__ __forceinline__ uint32_t smem_u32(const void* p) {
    uint32_t a;
    asm("{ .reg .u64 t; cvta.to.shared.u64 t, %1; cvt.u32.u64 %0, t; }"
        : "=r"(a) : "l"(p));
    return a;
}
// pack (lo,hi) -> bf16x2 word, lo in low 16 bits
__device__ __forceinline__ uint32_t bfpack(float lo, float hi) {
    uint32_t r;
    asm("cvt.rn.bf16x2.f32 %0, %1, %2;" : "=r"(r) : "f"(hi), "f"(lo));
    return r;
}
__device__ __forceinline__ void ldsm_x4(uint32_t& r0, uint32_t& r1,
                                        uint32_t& r2, uint32_t& r3, uint32_t a) {
    asm volatile("ldmatrix.sync.aligned.m8n8.x4.shared.b16 {%0,%1,%2,%3}, [%4];"
                 : "=r"(r0), "=r"(r1), "=r"(r2), "=r"(r3) : "r"(a));
}
__device__ __forceinline__ void ldsm_x4t(uint32_t& r0, uint32_t& r1,
                                         uint32_t& r2, uint32_t& r3, uint32_t a) {
    asm volatile("ldmatrix.sync.aligned.m8n8.x4.trans.shared.b16 {%0,%1,%2,%3}, [%4];"
                 : "=r"(r0), "=r"(r1), "=r"(r2), "=r"(r3) : "r"(a));
}
__device__ __forceinline__ void mma16816(float* c, const uint32_t* a,
                                         uint32_t b0, uint32_t b1) {
    asm volatile(
        "mma.sync.aligned.m16n8k16.row.col.f32.bf16.bf16.f32 "
        "{%0,%1,%2,%3}, {%4,%5,%6,%7}, {%8,%9}, {%0,%1,%2,%3};"
        : "+f"(c[0]), "+f"(c[1]), "+f"(c[2]), "+f"(c[3])
        : "r"(a[0]), "r"(a[1]), "r"(a[2]), "r"(a[3]), "r"(b0), "r"(b1));
}
// split 8 consecutive fp32 into 4 high-words + 4 low-words (bf16x2)
__device__ __forceinline__ void split8(const float* f, uint32_t* hw, uint32_t* lw) {
#pragma unroll
    for (int j = 0; j < 4; j++) {
        float f0 = f[2 * j], f1 = f[2 * j + 1];
        uint32_t h = bfpack(f0, f1);
        float l0 = f0 - __uint_as_float(h << 16);
        float l1 = f1 - __uint_as_float(h & 0xFFFF0000u);
        hw[j] = h;
        lw[j] = bfpack(l0, l1);
    }
}

// ---------------------------------------------------------------------------
// Kernel 2: grouped GEMM via mma.sync bf16 3-split.
// grid = (H/TN, N_HEADS, N_ROWS/TM); 256 threads (8 warps, 2m x 4n).
// ---------------------------------------------------------------------------
__global__ __launch_bounds__(256, 2)
void multilinear_mma(const float* __restrict__ X,
                     const float* __restrict__ W,
                     const float* __restrict__ Bb,
                     float* __restrict__ out) {
    const int h    = blockIdx.y;
    const int base = g_off[h];
    const int end  = g_off[h + 1];
    const int row0 = base + blockIdx.z * TM;
    if (row0 >= end) return;
    const int n0 = blockIdx.x * TN;

    __shared__ __align__(16) uint16_t Ah[TM * ASTRIDE];
    __shared__ __align__(16) uint16_t Al[TM * ASTRIDE];
    __shared__ __align__(16) uint16_t Wh[BK * WSTRIDE];
    __shared__ __align__(16) uint16_t Wl[BK * WSTRIDE];

    const int tid  = threadIdx.x;
    const int wid  = tid >> 5;
    const int lane = tid & 31;

    // ---- conversion-phase mappings ----
    // A: thread -> m = tid/4 (0..63), k-quarter kq = (tid%4)*8
    const int am = tid >> 2;
    const int kq = (tid & 3) * 8;
    const int arowg = row0 + am;
    const int agr   = (arowg < end) ? g_perm[arowg] : g_perm[row0];
    const float* aptr = X + (size_t)agr * D_DIM + kq;
    // W: thread -> k-row wk = tid/8 (0..31), n-chunk wn = (tid%8)*8
    const int wk = tid >> 3;
    const int wn = (tid & 7) * 8;
    const float* wptr = W + (size_t)h * D_DIM * H_DIM + (size_t)wk * H_DIM + n0 + wn;

    // ---- mma-phase mappings (warp tile 32x16; 2m x 4n warps) ----
    const int mw = (wid & 1) * 32;
    const int nw = (wid >> 1) * 16;
    // A ldmatrix lane address parts
    const int a_row = mw + (lane & 7) + 8 * ((lane >> 3) & 1);
    const int a_col = 8 * (lane >> 4);
    // B ldmatrix(trans) lane address parts
    const int b_krow = (lane & 7) + 8 * ((lane >> 3) & 1);
    const int b_ncol = nw + 8 * (lane >> 4);

    const uint32_t sAh = smem_u32(Ah), sAl = smem_u32(Al);
    const uint32_t sWh = smem_u32(Wh), sWl = smem_u32(Wl);

    float acc[2][2][4];
#pragma unroll
    for (int i = 0; i < 2; i++)
#pragma unroll
        for (int j = 0; j < 2; j++)
#pragma unroll
            for (int q = 0; q < 4; q++) acc[i][j][q] = 0.f;

    // prefetch tile 0
    float4 va[2], vw[2];
    va[0] = *reinterpret_cast<const float4*>(aptr);
    va[1] = *reinterpret_cast<const float4*>(aptr + 4);
    vw[0] = *reinterpret_cast<const float4*>(wptr);
    vw[1] = *reinterpret_cast<const float4*>(wptr + 4);

    for (int t = 0; t < KTILES; t++) {
        // ---- convert + STS tile t ----
        {
            uint32_t hw[4], lw[4];
            split8(reinterpret_cast<const float*>(va), hw, lw);
            *reinterpret_cast<uint4*>(&Ah[am * ASTRIDE + kq]) =
                make_uint4(hw[0], hw[1], hw[2], hw[3]);
            *reinterpret_cast<uint4*>(&Al[am * ASTRIDE + kq]) =
                make_uint4(lw[0], lw[1], lw[2], lw[3]);
            split8(reinterpret_cast<const float*>(vw), hw, lw);
            *reinterpret_cast<uint4*>(&Wh[wk * WSTRIDE + wn]) =
                make_uint4(hw[0], hw[1], hw[2], hw[3]);
            *reinterpret_cast<uint4*>(&Wl[wk * WSTRIDE + wn]) =
                make_uint4(lw[0], lw[1], lw[2], lw[3]);
        }
        // ---- prefetch tile t+1 (latency hidden under mma below) ----
        if (t + 1 < KTILES) {
            const float* ap = aptr + (t + 1) * BK;
            const float* wp = wptr + (size_t)(t + 1) * BK * H_DIM;
            va[0] = *reinterpret_cast<const float4*>(ap);
            va[1] = *reinterpret_cast<const float4*>(ap + 4);
            vw[0] = *reinterpret_cast<const float4*>(wp);
            vw[1] = *reinterpret_cast<const float4*>(wp + 4);
        }
        __syncthreads();

        // ---- mma over 2 ksteps x 3 splits ----
#pragma unroll
        for (int ks = 0; ks < 2; ks++) {
            const int k0 = ks * 16;
            uint32_t ah[2][4], al[2][4], wh[4], wl[4];
#pragma unroll
            for (int mi = 0; mi < 2; mi++) {
                uint32_t aoff = (uint32_t)(((a_row + mi * 16) * ASTRIDE + k0 + a_col) * 2);
                ldsm_x4(ah[mi][0], ah[mi][1], ah[mi][2], ah[mi][3], sAh + aoff);
                ldsm_x4(al[mi][0], al[mi][1], al[mi][2], al[mi][3], sAl + aoff);
            }
            {
                uint32_t boff = (uint32_t)(((k0 + b_krow) * WSTRIDE + b_ncol) * 2);
                ldsm_x4t(wh[0], wh[1], wh[2], wh[3], sWh + boff);
                ldsm_x4t(wl[0], wl[1], wl[2], wl[3], sWl + boff);
            }
#pragma unroll
            for (int mi = 0; mi < 2; mi++) {
#pragma unroll
                for (int ni = 0; ni < 2; ni++) {
                    mma16816(acc[mi][ni], ah[mi], wh[2 * ni], wh[2 * ni + 1]); // Ah*Wh
                    mma16816(acc[mi][ni], ah[mi], wl[2 * ni], wl[2 * ni + 1]); // Ah*Wl
                    mma16816(acc[mi][ni], al[mi], wh[2 * ni], wh[2 * ni + 1]); // Al*Wh
                }
            }
        }
        __syncthreads();
    }

    // ---- epilogue: bias + scatter to original rows ----
    const float* bp = Bb + (size_t)h * H_DIM;
#pragma unroll
    for (int mi = 0; mi < 2; mi++) {
#pragma unroll
        for (int half = 0; half < 2; half++) {
            const int rloc = mw + mi * 16 + (lane >> 2) + 8 * half;
            const int r    = row0 + rloc;
            if (r < end) {
                const int orow = g_perm[r];
                float* op = out + (size_t)orow * H_DIM;
#pragma unroll
                for (int ni = 0; ni < 2; ni++) {
                    const int c = n0 + nw + ni * 8 + 2 * (lane & 3);
                    float2 v;
                    v.x = acc[mi][ni][2 * half + 0] + bp[c];
                    v.y = acc[mi][ni][2 * half + 1] + bp[c + 1];
                    *reinterpret_cast<float2*>(op + c) = v;
                }
            }
        }
    }
}

// ---------------------------------------------------------------------------
extern "C" void kernel_launch(void* const* d_in, const int* in_sizes, int n_in,
                              void* d_out, int out_size) {
    const float* X = nullptr; const int* idx = nullptr;
    const float* W = nullptr; const float* B = nullptr;
    for (int i = 0; i < n_in; i++) {
        switch (in_sizes[i]) {
            case 1048576: X   = (const float*)d_in[i]; break;
            case 2048:    idx = (const int*)d_in[i];   break;
            case 4194304: W   = (const float*)d_in[i]; break;
            case 8192:    B   = (const float*)d_in[i]; break;
        }
    }
    float* out = (float*)d_out;

    bucket_kernel<<<1, 256>>>(idx);

    dim3 grid(H_DIM / TN, N_HEADS, N_ROWS / TM);
    multilinear_mma<<<grid, 256>>>(X, W, B, out);
}